// round 11
// baseline (speedup 1.0000x reference)
#include <cuda_runtime.h>
#include <cuda_bf16.h>
#include <cstdint>

// Problem constants
#define B_  8
#define T_  32
#define S_  512
#define F_  128
#define K_  64
#define N_  200

// Tiling
#define SI  32          // s-tile
#define FI  8           // f-tile
#define NT  128         // threads per block (4 warps)
#define KC  16          // k's per pipeline chunk
#define NCHUNK (K_/KC)  // 4

// SMEM (bytes):
//   Vbuf:  2 x KC*FI*SI floats = 32768  (double buffer, TMA-filled)
//   attnF: K*T floats          = 8192
//   mbars: 2 x 8                = 16
//   stgU:  (T/2)*SI*10 ull     = 40960  (overlays Vbuf+attnF after main loop)
#define SMEM_VBUF_BYTES  (KC*FI*SI*4)
#define SMEM_ATTN_BYTES  (K_*T_*4)
#define SMEM_MBAR_OFF    (2*SMEM_VBUF_BYTES + SMEM_ATTN_BYTES)   // 40960
#define SMEM_TOTAL       (SMEM_MBAR_OFF + 16)                    // 40976

typedef unsigned long long ull;

// Packed f32x2 FMA: acc = v * a + acc   (lanes = two adjacent t's)
__device__ __forceinline__ void fma2(ull& acc, ull v, ull a) {
    asm("fma.rn.f32x2 %0, %1, %2, %0;" : "+l"(acc) : "l"(v), "l"(a));
}
// Duplicate one fp32 into both lanes of an f32x2 register pair.
__device__ __forceinline__ ull dup2(float w) {
    ull r;
    asm("mov.b64 %0, {%1, %1};" : "=l"(r) : "f"(w));
    return r;
}
__device__ __forceinline__ uint32_t smem_u32(const void* p) {
    uint32_t a;
    asm("{ .reg .u64 t; cvta.to.shared.u64 t, %1; cvt.u32.u64 %0, t; }"
        : "=r"(a) : "l"(p));
    return a;
}
#define MBAR_INIT(a, c) \
    asm volatile("mbarrier.init.shared.b64 [%0], %1;" :: "r"(a), "r"((uint32_t)(c)) : "memory")
#define MBAR_EXPECT_TX(a, n) \
    asm volatile("mbarrier.arrive.expect_tx.shared.b64 _, [%0], %1;" :: "r"(a), "r"((uint32_t)(n)) : "memory")
#define MBAR_WAIT(mb, ph) do {                                              \
    uint32_t _m = (mb), _p = (ph), _d;                                      \
    asm volatile("{ .reg .pred p;"                                          \
        "mbarrier.try_wait.parity.acquire.cta.shared::cta.b64 p, [%1], %2;" \
        "selp.b32 %0, 1, 0, p; }" : "=r"(_d) : "r"(_m), "r"(_p) : "memory");\
    if (!_d) {                                                              \
        asm volatile("{ .reg .pred P1;"                                     \
            "WL_%=:"                                                        \
            "mbarrier.try_wait.parity.acquire.cta.shared::cta.b64 P1, [%0], %1, 0x989680;" \
            "@P1 bra.uni WD_%=;"                                            \
            "bra.uni WL_%=;"                                                \
            "WD_%=: }" :: "r"(_m), "r"(_p) : "memory");                     \
    } } while (0)
// 1D TMA bulk copy: 128 contiguous bytes global -> shared, complete_tx on mbar.
__device__ __forceinline__ void bulk128(float* smem_dst, const float* gsrc,
                                        uint32_t mbar) {
    uint32_t d = smem_u32(smem_dst);
    asm volatile(
        "cp.async.bulk.shared::cluster.global.mbarrier::complete_tx::bytes "
        "[%0], [%1], 128, [%2];"
        :: "r"(d), "l"(gsrc), "r"(mbar) : "memory");
}

// ---------------------------------------------------------------------------
// Grid: (S/SI, F/FI, B) = (16,16,8) = 2048 blocks, 128 threads, 4 CTAs/SM.
// Thread (sg, fl, tq): 4 s x 1 f x 16 t (8 f32x2 t-pairs).  [R6 structure]
// V fill: warp 0 issues 128 x 128B TMA bulk rows per chunk (double buffered).
// ---------------------------------------------------------------------------
__global__ void __launch_bounds__(NT, 4)
fusion_kernel(const float* __restrict__ tgt,
              const float* __restrict__ V,
              const float* __restrict__ corr,
              const int*   __restrict__ tIdx,
              const int*   __restrict__ rIdx,
              float* __restrict__ out) {
    extern __shared__ char smem[];
    float* Vb[2] = { (float*)smem, (float*)(smem + SMEM_VBUF_BYTES) };
    float* attnF = (float*)(smem + 2 * SMEM_VBUF_BYTES);   // [K][T]
    ull*   stgU  = (ull*)smem;                              // overlay after loop
    const uint32_t mb0 = smem_u32(smem + SMEM_MBAR_OFF);

    const int b   = blockIdx.z;
    const int f0  = blockIdx.y * FI;
    const int s0  = blockIdx.x * SI;
    const int tid = threadIdx.x;
    const int wid  = tid >> 5;
    const int lane = tid & 31;

    const float* Vg = V + (long)b * K_ * F_ * S_ + (long)f0 * S_ + s0;

    // issue chunk c into buffer c&1 (warp 0 only; 4 rows per lane)
    auto issue_chunk = [&](int c) {
        uint32_t mb = mb0 + (c & 1) * 8;
        MBAR_EXPECT_TX(mb, 512);   // this lane's 4 x 128B
        float* dst = Vb[c & 1];
        const float* src = Vg + (long)c * KC * F_ * S_;
        #pragma unroll
        for (int i = 0; i < 4; ++i) {
            int r = lane * 4 + i;        // 0..127 : r = k*8 + f
            int k = r >> 3;
            int f = r & 7;
            bulk128(dst + (k * FI + f) * SI,
                    src + (long)k * F_ * S_ + (long)f * S_, mb);
        }
    };

    // --- init mbars + prefetch chunk 0 (warp 0; latency hidden by softmax) ---
    if (wid == 0) {
        if (lane == 0) {
            MBAR_INIT(mb0, 32);
            MBAR_INIT(mb0 + 8, 32);
        }
        __syncwarp();
        issue_chunk(0);
    }

    // --- softmax: 4 warps x 8 t's each, gather from L2-hot corr ---
    {
        int c0 = rIdx[lane];
        int c1 = rIdx[lane + 32];
        #pragma unroll
        for (int t = wid; t < T_; t += 4) {
            int row = tIdx[b * T_ + t];
            float v0 = __ldg(corr + row * N_ + c0);
            float v1 = __ldg(corr + row * N_ + c1);
            float m = fmaxf(v0, v1);
            #pragma unroll
            for (int off = 16; off > 0; off >>= 1)
                m = fmaxf(m, __shfl_xor_sync(0xffffffffu, m, off));
            float e0 = expf(v0 - m);
            float e1 = expf(v1 - m);
            float s = e0 + e1;
            #pragma unroll
            for (int off = 16; off > 0; off >>= 1)
                s += __shfl_xor_sync(0xffffffffu, s, off);
            float inv = 1.0f / s;
            attnF[lane * T_ + t]        = e0 * inv;
            attnF[(lane + 32) * T_ + t] = e1 * inv;
        }
    }
    __syncthreads();   // publishes attnF and mbar inits to all warps

    // --- main loop: TMA double-buffered k-chunks ---
    const int sg = tid & 7;           // 0..7 : s-group (4 s each)
    const int fl = (tid >> 3) & 7;    // 0..7 : f within tile
    const int tq = tid >> 6;          // 0..1 : t-half
    const int t0 = tq * 16;

    ull acc[8][4];
    #pragma unroll
    for (int p = 0; p < 8; ++p)
        #pragma unroll
        for (int si = 0; si < 4; ++si) acc[p][si] = 0ULL;

    #pragma unroll
    for (int c = 0; c < NCHUNK; ++c) {
        MBAR_WAIT(mb0 + (c & 1) * 8, (c >> 1) & 1);   // chunk c resident
        // warp 0: refill the other buffer with chunk c+1
        // (safe: chunk c-1 reads finished at previous end-of-iter barrier)
        if (wid == 0 && c + 1 < NCHUNK) issue_chunk(c + 1);

        const float* Vc = Vb[c & 1];
        const float* aFc = attnF + c * KC * T_;
        #pragma unroll 4
        for (int k = 0; k < KC; ++k) {
            float4 vf = *(const float4*)(Vc + (k * FI + fl) * SI + sg * 4);
            ull vd0 = dup2(vf.x), vd1 = dup2(vf.y);
            ull vd2 = dup2(vf.z), vd3 = dup2(vf.w);
            const float* aF = aFc + k * T_ + t0;
            ulonglong2 a01 = *(const ulonglong2*)(aF);
            ulonglong2 a23 = *(const ulonglong2*)(aF + 4);
            ulonglong2 a45 = *(const ulonglong2*)(aF + 8);
            ulonglong2 a67 = *(const ulonglong2*)(aF + 12);
            fma2(acc[0][0], vd0, a01.x); fma2(acc[0][1], vd1, a01.x);
            fma2(acc[0][2], vd2, a01.x); fma2(acc[0][3], vd3, a01.x);
            fma2(acc[1][0], vd0, a01.y); fma2(acc[1][1], vd1, a01.y);
            fma2(acc[1][2], vd2, a01.y); fma2(acc[1][3], vd3, a01.y);
            fma2(acc[2][0], vd0, a23.x); fma2(acc[2][1], vd1, a23.x);
            fma2(acc[2][2], vd2, a23.x); fma2(acc[2][3], vd3, a23.x);
            fma2(acc[3][0], vd0, a23.y); fma2(acc[3][1], vd1, a23.y);
            fma2(acc[3][2], vd2, a23.y); fma2(acc[3][3], vd3, a23.y);
            fma2(acc[4][0], vd0, a45.x); fma2(acc[4][1], vd1, a45.x);
            fma2(acc[4][2], vd2, a45.x); fma2(acc[4][3], vd3, a45.x);
            fma2(acc[5][0], vd0, a45.y); fma2(acc[5][1], vd1, a45.y);
            fma2(acc[5][2], vd2, a45.y); fma2(acc[5][3], vd3, a45.y);
            fma2(acc[6][0], vd0, a67.x); fma2(acc[6][1], vd1, a67.x);
            fma2(acc[6][2], vd2, a67.x); fma2(acc[6][3], vd3, a67.x);
            fma2(acc[7][0], vd0, a67.y); fma2(acc[7][1], vd1, a67.y);
            fma2(acc[7][2], vd2, a67.y); fma2(acc[7][3], vd3, a67.y);
        }
        __syncthreads();   // all warps done with chunk c before its buffer refills
    }

    // --- stage: stgU[tpair][s][10] (fl at 0..7, 2 pad); overlays V buffers ---
    #pragma unroll
    for (int p = 0; p < 8; ++p) {
        int tp = tq * 8 + p;
        #pragma unroll
        for (int si = 0; si < 4; ++si) {
            int s = sg * 4 + si;
            stgU[(tp * SI + s) * 10 + fl] = acc[p][si];
        }
    }
    __syncthreads();

    // --- epilogue: per iter read 4 ull (2 x LDS.128) -> two float4 RMW ---
    #pragma unroll
    for (int i = tid; i < (T_ / 2) * SI * 2; i += NT) {
        int g  = i & 1;
        int s  = (i >> 1) & (SI - 1);
        int tp = i >> 6;
        const ull* src = &stgU[(tp * SI + s) * 10 + 4 * g];
        ulonglong2 u0 = *(const ulonglong2*)(src);       // f = 4g, 4g+1
        ulonglong2 u1 = *(const ulonglong2*)(src + 2);   // f = 4g+2, 4g+3
        float2 p0 = *(const float2*)&u0.x;  // (t_even, t_odd)
        float2 p1 = *(const float2*)&u0.y;
        float2 p2 = *(const float2*)&u1.x;
        float2 p3 = *(const float2*)&u1.y;

        long gi0 = (((long)b * T_ + 2 * tp)     * S_ + s0 + s) * F_ + f0 + 4 * g;
        long gi1 = (((long)b * T_ + 2 * tp + 1) * S_ + s0 + s) * F_ + f0 + 4 * g;
        float4 t4, c4;
        t4 = *(const float4*)(tgt + gi0);
        c4.x = p0.x + t4.x; c4.y = p1.x + t4.y;
        c4.z = p2.x + t4.z; c4.w = p3.x + t4.w;
        *(float4*)(out + gi0) = c4;
        t4 = *(const float4*)(tgt + gi1);
        c4.x = p0.y + t4.x; c4.y = p1.y + t4.y;
        c4.z = p2.y + t4.z; c4.w = p3.y + t4.w;
        *(float4*)(out + gi1) = c4;
    }
}

// ---------------------------------------------------------------------------
extern "C" void kernel_launch(void* const* d_in, const int* in_sizes, int n_in,
                              void* d_out, int out_size) {
    const float* tgt  = nullptr;   // 16777216
    const float* V    = nullptr;   // 33554432
    const float* corr = nullptr;   // 40000
    const int*   tIdx = nullptr;   // 256   (int32: jax x64 disabled)
    const int*   rIdx = nullptr;   // 64

    for (int i = 0; i < n_in; ++i) {
        switch (in_sizes[i]) {
            case 16777216: tgt  = (const float*)d_in[i]; break;
            case 33554432: V    = (const float*)d_in[i]; break;
            case 40000:    corr = (const float*)d_in[i]; break;
            case 256:      tIdx = (const int*)d_in[i]; break;
            case 64:       rIdx = (const int*)d_in[i]; break;
            default: break;
        }
    }

    cudaFuncSetAttribute(fusion_kernel,
                         cudaFuncAttributeMaxDynamicSharedMemorySize,
                         SMEM_TOTAL);

    dim3 grid(S_ / SI, F_ / FI, B_);
    fusion_kernel<<<grid, NT, SMEM_TOTAL>>>(tgt, V, corr, tIdx, rIdx, (float*)d_out);
}

// round 12
// speedup vs baseline: 1.3804x; 1.3804x over previous
#include <cuda_runtime.h>
#include <cuda.h>
#include <cuda_bf16.h>
#include <cstdint>

// Problem constants
#define B_  8
#define T_  32
#define S_  512
#define F_  128
#define K_  64
#define N_  200

// Tiling
#define SI  32          // s-tile
#define FI  8           // f-tile
#define NT  128         // threads per block (4 warps)
#define KC  16          // k's per pipeline chunk
#define NCHUNK (K_/KC)  // 4
#define CHUNK_BYTES (KC*FI*SI*4)   // 16384

// SMEM (bytes):
//   Vbuf:  2 x 16KB = 32768  (double buffer, one TMA op each)
//   attnF: K*T floats = 8192
//   mbars: 2 x 8 = 16
//   stgU:  (T/2)*SI*10 ull = 40960 (overlays Vbuf+attnF after main loop)
#define SMEM_VBUF_BYTES  CHUNK_BYTES
#define SMEM_ATTN_BYTES  (K_*T_*4)
#define SMEM_MBAR_OFF    (2*SMEM_VBUF_BYTES + SMEM_ATTN_BYTES)   // 40960
#define SMEM_TOTAL       (SMEM_MBAR_OFF + 16)                    // 40976

typedef unsigned long long ull;

// Packed f32x2 FMA: acc = v * a + acc   (lanes = two adjacent t's)
__device__ __forceinline__ void fma2(ull& acc, ull v, ull a) {
    asm("fma.rn.f32x2 %0, %1, %2, %0;" : "+l"(acc) : "l"(v), "l"(a));
}
// Duplicate one fp32 into both lanes of an f32x2 register pair.
__device__ __forceinline__ ull dup2(float w) {
    ull r;
    asm("mov.b64 %0, {%1, %1};" : "=l"(r) : "f"(w));
    return r;
}
__device__ __forceinline__ uint32_t smem_u32(const void* p) {
    uint32_t a;
    asm("{ .reg .u64 t; cvta.to.shared.u64 t, %1; cvt.u32.u64 %0, t; }"
        : "=r"(a) : "l"(p));
    return a;
}
#define MBAR_INIT(a, c) \
    asm volatile("mbarrier.init.shared.b64 [%0], %1;" :: "r"(a), "r"((uint32_t)(c)) : "memory")
#define MBAR_EXPECT_TX(a, n) \
    asm volatile("mbarrier.arrive.expect_tx.shared.b64 _, [%0], %1;" :: "r"(a), "r"((uint32_t)(n)) : "memory")
#define MBAR_WAIT(mb, ph) do {                                              \
    uint32_t _m = (mb), _p = (ph), _d;                                      \
    asm volatile("{ .reg .pred p;"                                          \
        "mbarrier.try_wait.parity.acquire.cta.shared::cta.b64 p, [%1], %2;" \
        "selp.b32 %0, 1, 0, p; }" : "=r"(_d) : "r"(_m), "r"(_p) : "memory");\
    if (!_d) {                                                              \
        asm volatile("{ .reg .pred P1;"                                     \
            "WL_%=:"                                                        \
            "mbarrier.try_wait.parity.acquire.cta.shared::cta.b64 P1, [%0], %1, 0x989680;" \
            "@P1 bra.uni WD_%=;"                                            \
            "bra.uni WL_%=;"                                                \
            "WD_%=: }" :: "r"(_m), "r"(_p) : "memory");                     \
    } } while (0)
// 4D TMA tile load: 16KB box (s=32, f=8, k=16, b=1) global -> shared
__device__ __forceinline__ void tma4d(uint32_t dst, const CUtensorMap* tm,
                                      int cs, int cf, int ck, int cb,
                                      uint32_t mbar) {
    asm volatile(
        "cp.async.bulk.tensor.4d.shared::cta.global.tile.mbarrier::complete_tx::bytes "
        "[%0], [%1, {%2, %3, %4, %5}], [%6];"
        :: "r"(dst), "l"(tm), "r"(cs), "r"(cf), "r"(ck), "r"(cb), "r"(mbar)
        : "memory");
}

// ---------------------------------------------------------------------------
// Grid: (S/SI, F/FI, B) = (16,16,8) = 2048 blocks, 128 threads, 4 CTAs/SM.
// Thread (sg, fl, tq): 4 s x 1 f x 16 t (8 f32x2 t-pairs).  [R6 structure]
// V fill: ONE 16KB 4D-TMA op per chunk (tid 0), depth-2 double buffer.
// ---------------------------------------------------------------------------
__global__ void __launch_bounds__(NT, 4)
fusion_kernel(const float* __restrict__ tgt,
              const __grid_constant__ CUtensorMap tmap,
              const float* __restrict__ corr,
              const int*   __restrict__ tIdx,
              const int*   __restrict__ rIdx,
              float* __restrict__ out) {
    extern __shared__ char smem[];
    float* Vb[2] = { (float*)smem, (float*)(smem + SMEM_VBUF_BYTES) };
    float* attnF = (float*)(smem + 2 * SMEM_VBUF_BYTES);   // [K][T]
    ull*   stgU  = (ull*)smem;                              // overlay after loop
    const uint32_t mb0 = smem_u32(smem + SMEM_MBAR_OFF);
    const uint32_t vb0 = smem_u32(smem);

    const int b   = blockIdx.z;
    const int f0  = blockIdx.y * FI;
    const int s0  = blockIdx.x * SI;
    const int tid = threadIdx.x;
    const int wid  = tid >> 5;
    const int lane = tid & 31;

    // --- tid 0: init mbars, issue chunks 0 and 1 (latency hidden by softmax) ---
    if (tid == 0) {
        MBAR_INIT(mb0, 1);
        MBAR_INIT(mb0 + 8, 1);
        MBAR_EXPECT_TX(mb0, CHUNK_BYTES);
        tma4d(vb0, &tmap, s0, f0, 0, b, mb0);
        MBAR_EXPECT_TX(mb0 + 8, CHUNK_BYTES);
        tma4d(vb0 + SMEM_VBUF_BYTES, &tmap, s0, f0, KC, b, mb0 + 8);
    }

    // --- softmax: 4 warps x 8 t's each, gather from L2-hot corr ---
    {
        int c0 = rIdx[lane];
        int c1 = rIdx[lane + 32];
        #pragma unroll
        for (int t = wid; t < T_; t += 4) {
            int row = tIdx[b * T_ + t];
            float v0 = __ldg(corr + row * N_ + c0);
            float v1 = __ldg(corr + row * N_ + c1);
            float m = fmaxf(v0, v1);
            #pragma unroll
            for (int off = 16; off > 0; off >>= 1)
                m = fmaxf(m, __shfl_xor_sync(0xffffffffu, m, off));
            float e0 = expf(v0 - m);
            float e1 = expf(v1 - m);
            float s = e0 + e1;
            #pragma unroll
            for (int off = 16; off > 0; off >>= 1)
                s += __shfl_xor_sync(0xffffffffu, s, off);
            float inv = 1.0f / s;
            attnF[lane * T_ + t]        = e0 * inv;
            attnF[(lane + 32) * T_ + t] = e1 * inv;
        }
    }
    __syncthreads();   // publishes attnF and mbar inits to all warps

    // --- main loop: TMA double-buffered k-chunks ---
    const int sg = tid & 7;           // 0..7 : s-group (4 s each)
    const int fl = (tid >> 3) & 7;    // 0..7 : f within tile
    const int tq = tid >> 6;          // 0..1 : t-half
    const int t0 = tq * 16;

    ull acc[8][4];
    #pragma unroll
    for (int p = 0; p < 8; ++p)
        #pragma unroll
        for (int si = 0; si < 4; ++si) acc[p][si] = 0ULL;

    #pragma unroll
    for (int c = 0; c < NCHUNK; ++c) {
        MBAR_WAIT(mb0 + (c & 1) * 8, (c >> 1) & 1);   // chunk c resident

        const float* Vc = Vb[c & 1];
        const float* aFc = attnF + c * KC * T_;
        #pragma unroll 4
        for (int k = 0; k < KC; ++k) {
            float4 vf = *(const float4*)(Vc + (k * FI + fl) * SI + sg * 4);
            ull vd0 = dup2(vf.x), vd1 = dup2(vf.y);
            ull vd2 = dup2(vf.z), vd3 = dup2(vf.w);
            const float* aF = aFc + k * T_ + t0;
            ulonglong2 a01 = *(const ulonglong2*)(aF);
            ulonglong2 a23 = *(const ulonglong2*)(aF + 4);
            ulonglong2 a45 = *(const ulonglong2*)(aF + 8);
            ulonglong2 a67 = *(const ulonglong2*)(aF + 12);
            fma2(acc[0][0], vd0, a01.x); fma2(acc[0][1], vd1, a01.x);
            fma2(acc[0][2], vd2, a01.x); fma2(acc[0][3], vd3, a01.x);
            fma2(acc[1][0], vd0, a01.y); fma2(acc[1][1], vd1, a01.y);
            fma2(acc[1][2], vd2, a01.y); fma2(acc[1][3], vd3, a01.y);
            fma2(acc[2][0], vd0, a23.x); fma2(acc[2][1], vd1, a23.x);
            fma2(acc[2][2], vd2, a23.x); fma2(acc[2][3], vd3, a23.x);
            fma2(acc[3][0], vd0, a23.y); fma2(acc[3][1], vd1, a23.y);
            fma2(acc[3][2], vd2, a23.y); fma2(acc[3][3], vd3, a23.y);
            fma2(acc[4][0], vd0, a45.x); fma2(acc[4][1], vd1, a45.x);
            fma2(acc[4][2], vd2, a45.x); fma2(acc[4][3], vd3, a45.x);
            fma2(acc[5][0], vd0, a45.y); fma2(acc[5][1], vd1, a45.y);
            fma2(acc[5][2], vd2, a45.y); fma2(acc[5][3], vd3, a45.y);
            fma2(acc[6][0], vd0, a67.x); fma2(acc[6][1], vd1, a67.x);
            fma2(acc[6][2], vd2, a67.x); fma2(acc[6][3], vd3, a67.x);
            fma2(acc[7][0], vd0, a67.y); fma2(acc[7][1], vd1, a67.y);
            fma2(acc[7][2], vd2, a67.y); fma2(acc[7][3], vd3, a67.y);
        }
        __syncthreads();   // all warps done reading buffer (c&1)
        // refill this buffer with chunk c+2
        if (tid == 0 && c + 2 < NCHUNK) {
            uint32_t mb = mb0 + (c & 1) * 8;
            MBAR_EXPECT_TX(mb, CHUNK_BYTES);
            tma4d(vb0 + (c & 1) * SMEM_VBUF_BYTES, &tmap,
                  s0, f0, (c + 2) * KC, b, mb);
        }
    }

    // --- stage: stgU[tpair][s][10] (fl at 0..7, 2 pad); overlays V buffers ---
    #pragma unroll
    for (int p = 0; p < 8; ++p) {
        int tp = tq * 8 + p;
        #pragma unroll
        for (int si = 0; si < 4; ++si) {
            int s = sg * 4 + si;
            stgU[(tp * SI + s) * 10 + fl] = acc[p][si];
        }
    }
    __syncthreads();

    // --- epilogue: per iter read 4 ull (2 x LDS.128) -> two float4 RMW ---
    #pragma unroll
    for (int i = tid; i < (T_ / 2) * SI * 2; i += NT) {
        int g  = i & 1;
        int s  = (i >> 1) & (SI - 1);
        int tp = i >> 6;
        const ull* src = &stgU[(tp * SI + s) * 10 + 4 * g];
        ulonglong2 u0 = *(const ulonglong2*)(src);       // f = 4g, 4g+1
        ulonglong2 u1 = *(const ulonglong2*)(src + 2);   // f = 4g+2, 4g+3
        float2 p0 = *(const float2*)&u0.x;  // (t_even, t_odd)
        float2 p1 = *(const float2*)&u0.y;
        float2 p2 = *(const float2*)&u1.x;
        float2 p3 = *(const float2*)&u1.y;

        long gi0 = (((long)b * T_ + 2 * tp)     * S_ + s0 + s) * F_ + f0 + 4 * g;
        long gi1 = (((long)b * T_ + 2 * tp + 1) * S_ + s0 + s) * F_ + f0 + 4 * g;
        float4 t4, c4;
        t4 = *(const float4*)(tgt + gi0);
        c4.x = p0.x + t4.x; c4.y = p1.x + t4.y;
        c4.z = p2.x + t4.z; c4.w = p3.x + t4.w;
        *(float4*)(out + gi0) = c4;
        t4 = *(const float4*)(tgt + gi1);
        c4.x = p0.y + t4.x; c4.y = p1.y + t4.y;
        c4.z = p2.y + t4.z; c4.w = p3.y + t4.w;
        *(float4*)(out + gi1) = c4;
    }
}

// ---------------------------------------------------------------------------
typedef CUresult (*PFN_tmapEncode)(
    CUtensorMap*, CUtensorMapDataType, cuuint32_t, void*,
    const cuuint64_t*, const cuuint64_t*, const cuuint32_t*, const cuuint32_t*,
    CUtensorMapInterleave, CUtensorMapSwizzle, CUtensorMapL2promotion,
    CUtensorMapFloatOOBfill);

extern "C" void kernel_launch(void* const* d_in, const int* in_sizes, int n_in,
                              void* d_out, int out_size) {
    const float* tgt  = nullptr;   // 16777216
    const float* V    = nullptr;   // 33554432
    const float* corr = nullptr;   // 40000
    const int*   tIdx = nullptr;   // 256   (int32: jax x64 disabled)
    const int*   rIdx = nullptr;   // 64

    for (int i = 0; i < n_in; ++i) {
        switch (in_sizes[i]) {
            case 16777216: tgt  = (const float*)d_in[i]; break;
            case 33554432: V    = (const float*)d_in[i]; break;
            case 40000:    corr = (const float*)d_in[i]; break;
            case 256:      tIdx = (const int*)d_in[i]; break;
            case 64:       rIdx = (const int*)d_in[i]; break;
            default: break;
        }
    }

    // Build the 4D TMA descriptor (driver entry point; no -lcuda needed).
    static PFN_tmapEncode encode = nullptr;
    if (!encode) {
        void* fp = nullptr;
        cudaGetDriverEntryPoint("cuTensorMapEncodeTiled", &fp,
                                cudaEnableDefault);
        encode = (PFN_tmapEncode)fp;
    }
    CUtensorMap tmap;
    {
        cuuint64_t dims[4]    = { S_, F_, K_, B_ };          // s, f, k, b
        cuuint64_t strides[3] = { (cuuint64_t)S_ * 4,
                                  (cuuint64_t)F_ * S_ * 4,
                                  (cuuint64_t)K_ * F_ * S_ * 4 };
        cuuint32_t box[4]     = { SI, FI, KC, 1 };
        cuuint32_t estr[4]    = { 1, 1, 1, 1 };
        encode(&tmap, CU_TENSOR_MAP_DATA_TYPE_FLOAT32, 4, (void*)V,
               dims, strides, box, estr,
               CU_TENSOR_MAP_INTERLEAVE_NONE, CU_TENSOR_MAP_SWIZZLE_NONE,
               CU_TENSOR_MAP_L2_PROMOTION_L2_128B,
               CU_TENSOR_MAP_FLOAT_OOB_FILL_NONE);
    }

    cudaFuncSetAttribute(fusion_kernel,
                         cudaFuncAttributeMaxDynamicSharedMemorySize,
                         SMEM_TOTAL);

    dim3 grid(S_ / SI, F_ / FI, B_);
    fusion_kernel<<<grid, NT, SMEM_TOTAL>>>(tgt, tmap, corr, tIdx, rIdx,
                                            (float*)d_out);
}